// round 14
// baseline (speedup 1.0000x reference)
#include <cuda_runtime.h>
#include <math.h>
#include <stdint.h>

#define S_STEPS 128
#define NNODE   32
#define DIM     300
#define NREL    4
#define NEDGE   64
#define VOUT    50000
#define VB      ((VOUT + 63) / 64)     // 782 logits col-blocks

#define KS_GX 1200   // ksteps for GX (K=9600)
#define KS_X1 40     // ksteps for X1 (K padded 300->320)

// ---------------- scratch (device globals; no allocs allowed) ----------------
__device__ __align__(16) float g_GX[S_STEPS * NNODE * DIM];   // gathered features [s][n*d]
__device__ __align__(16) float g_Y [S_STEPS * NREL * DIM];    // weighted node sums [s][r][d]
__device__ __align__(16) float g_A [S_STEPS * DIM];           // gxflat @ Wg
__device__ __align__(16) float g_P0[S_STEPS * DIM];           // proposed row 0
__device__ __align__(16) float g_X1[S_STEPS * DIM];           // leaky_relu(new[0]) per step
__device__ float g_sub[S_STEPS];                              // logsumexp per row
__device__ __align__(16) float g_FGX[8 * KS_GX * 32 * 4];     // frag-order GX (4.7MB)
__device__ __align__(16) float g_FA1[8 * KS_X1 * 32 * 4];     // frag-order X1 (160KB)
__device__ __align__(8)  float2 g_plse[(size_t)VB * S_STEPS]; // per-(vblock,row) partial (max,sumexp)

// ---------------- helpers ----------------
__device__ __forceinline__ uint32_t smem_u32(const void* p) {
    uint32_t a;
    asm("{ .reg .u64 t; cvta.to.shared.u64 t, %1; cvt.u32.u64 %0, t; }" : "=r"(a) : "l"(p));
    return a;
}
__device__ __forceinline__ void st_cluster_f32(uint32_t saddr, uint32_t rank, float v) {
    uint32_t remote;
    asm volatile("mapa.shared::cluster.u32 %0, %1, %2;" : "=r"(remote) : "r"(saddr), "r"(rank));
    asm volatile("st.shared::cluster.b32 [%0], %1;" :: "r"(remote), "r"(__float_as_int(v)) : "memory");
}
// D += A(16x8) * B(8x8), tf32 inputs, fp32 accum
__device__ __forceinline__ void mma8(float* c, const float4& a, float b0, float b1) {
    asm volatile(
        "mma.sync.aligned.m16n8k8.row.col.f32.tf32.tf32.f32 "
        "{%0,%1,%2,%3}, {%4,%5,%6,%7}, {%8,%9}, {%0,%1,%2,%3};"
        : "+f"(c[0]), "+f"(c[1]), "+f"(c[2]), "+f"(c[3])
        : "r"(__float_as_uint(a.x)), "r"(__float_as_uint(a.y)),
          "r"(__float_as_uint(a.z)), "r"(__float_as_uint(a.w)),
          "r"(__float_as_uint(b0)), "r"(__float_as_uint(b1)));
}
// online (max, sumexp) update with one value
__device__ __forceinline__ void lse_upd(float& m, float& s, float v) {
    if (v > m) { s = s * __expf(m - v) + 1.0f; m = v; }
    else       { s += __expf(v - m); }
}
__device__ __forceinline__ void lse_merge(float& m, float& s, float om, float os) {
    float M = fmaxf(m, om);
    s = s * __expf(m - M) + os * __expf(om - M);
    m = M;
}

// ---------------- K1: fused gather + graph prep + zero ----------------
__global__ void k_gp(const int* __restrict__ xind, const int* __restrict__ eidx,
                     const int* __restrict__ etyp, const float* __restrict__ X,
                     float* __restrict__ senses) {
    int s = blockIdx.x;
    int tid = threadIdx.x;                              // 256 threads
    __shared__ int idx[NNODE];
    __shared__ __align__(16) float gxs[NNODE * DIM];    // 38.4KB
    __shared__ int ssrc[NEDGE], sdst[NEDGE], styp[NEDGE];
    __shared__ int degc[NREL][NNODE];
    __shared__ float dis[NREL][NNODE];
    __shared__ float w[NREL][NNODE];

    if (tid < NNODE) idx[tid] = xind[s * NNODE + tid];
    if (tid < NEDGE) {
        ssrc[tid] = eidx[s * (2 * NEDGE) + tid];
        sdst[tid] = eidx[s * (2 * NEDGE) + NEDGE + tid];
        styp[tid] = etyp[s * NEDGE + tid];
    }
    if (tid < NREL * NNODE) ((int*)degc)[tid] = 0;
    __syncthreads();

    // gather: X rows -> smem + global
    const float4* Xv = (const float4*)X;
    float4* Gv = (float4*)(g_GX + s * (NNODE * DIM));
    float4* Sv = (float4*)gxs;
    for (int f = tid; f < NNODE * (DIM / 4); f += blockDim.x) {
        int n = f / (DIM / 4), j = f % (DIM / 4);
        float4 v = Xv[(size_t)idx[n] * (DIM / 4) + j];
        Gv[f] = v; Sv[f] = v;
    }
    if (tid < NEDGE) atomicAdd(&degc[styp[tid]][sdst[tid]], 1);
    __syncthreads();
    if (tid < NREL * NNODE) {
        int r = tid >> 5, n = tid & 31;
        dis[r][n] = rsqrtf((float)degc[r][n] + 1.0f);
        ((float*)w)[tid] = 0.0f;
    }
    __syncthreads();
    if (tid < NEDGE && sdst[tid] == 0) {
        int r = styp[tid], sr = ssrc[tid];
        atomicAdd(&w[r][sr], dis[r][sr] * dis[r][0]);
    }
    __syncthreads();
    if (tid < NREL) w[tid][0] += dis[tid][0] * dis[tid][0];
    __syncthreads();
    for (int r = 0; r < NREL; r++) {
        for (int d = tid; d < DIM; d += blockDim.x) {
            float acc = 0.0f;
            #pragma unroll 1
            for (int n = 0; n < NNODE; n++) {
                float ww = w[r][n];
                if (ww != 0.0f) acc = fmaf(ww, gxs[n * DIM + d], acc);
            }
            g_Y[s * (NREL * DIM) + r * DIM + d] = acc;
        }
    }
    // zero accumulators for the gemm atomics + senses output
    for (int d = tid; d < DIM; d += blockDim.x) {
        g_A [s * DIM + d] = 0.0f;
        g_P0[s * DIM + d] = 0.0f;
    }
    if (tid == 0) senses[s] = 0.0f;
}

// ---------------- K2: fragGX (vectorized: 4xLDG.128 -> 4xSTG.128 per thread) ----------------
__global__ void k_fragGX() {
    int t = blockIdx.x * blockDim.x + threadIdx.x;   // 8 * KS_GX * 8 = 76800
    if (t >= 8 * KS_GX * 8) return;
    int g  = t & 7;
    int ks = (t >> 3) % KS_GX;
    int mt = t / (8 * KS_GX);
    int r0 = mt * 16 + g, r1 = r0 + 8;
    const float4* p0 = (const float4*)(g_GX + r0 * (NNODE * DIM) + ks * 8);
    const float4* p1 = (const float4*)(g_GX + r1 * (NNODE * DIM) + ks * 8);
    float4 a0 = p0[0], b0 = p0[1];
    float4 a1 = p1[0], b1 = p1[1];
    float4* o = (float4*)(g_FGX + ((size_t)(mt * KS_GX + ks) * 32 + g * 4) * 4);
    o[0] = make_float4(a0.x, a1.x, b0.x, b1.x);
    o[1] = make_float4(a0.y, a1.y, b0.y, b1.y);
    o[2] = make_float4(a0.z, a1.z, b0.z, b1.z);
    o[3] = make_float4(a0.w, a1.w, b0.w, b1.w);
}

// ---------------- fragX1 (small, padded 300->320) ----------------
__global__ void k_fragX1() {
    int total = 8 * KS_X1 * 32;
    for (int idx = blockIdx.x * blockDim.x + threadIdx.x; idx < total;
         idx += gridDim.x * blockDim.x) {
        int lane = idx & 31;
        int ks   = (idx >> 5) % KS_X1;
        int mt   = idx / (32 * KS_X1);
        int g = lane >> 2, t4 = lane & 3;
        int r0 = mt * 16 + g, r1 = r0 + 8;
        int k0 = ks * 8 + t4;
        float4 v;
        v.x = (k0     < DIM) ? g_X1[r0 * DIM + k0]     : 0.0f;
        v.y = (k0     < DIM) ? g_X1[r1 * DIM + k0]     : 0.0f;
        v.z = (k0 + 4 < DIM) ? g_X1[r0 * DIM + k0 + 4] : 0.0f;
        v.w = (k0 + 4 < DIM) ? g_X1[r1 * DIM + k0 + 4] : 0.0f;
        *(float4*)(g_FA1 + (size_t)idx * 4) = v;
    }
}

// ---------------- K4: A = GXflat[128,9600] @ Wg[9600,300]  (tf32 mma, k-split atomic) ----------------
__global__ void k_gemmA_mma(const float* __restrict__ Wg) {
    const int n0  = blockIdx.x * 64;     // 5 col tiles
    const int ksp = blockIdx.y;          // 30 k splits, 320 k each
    __shared__ float Bs[80][68];
    int tid = threadIdx.x;
    int w = tid >> 5, lane = tid & 31;
    int g = lane >> 2, t4 = lane & 3;
    int wm = w & 3, wn = w >> 2;
    float acc[2][4][4];
    #pragma unroll
    for (int a = 0; a < 2; a++)
        #pragma unroll
        for (int b = 0; b < 4; b++)
            #pragma unroll
            for (int c = 0; c < 4; c++) acc[a][b][c] = 0.0f;

    int nn  = tid & 63;
    int kk0 = (tid >> 6) * 20;
    bool nok = (n0 + nn) < DIM;
    for (int c = 0; c < 4; c++) {
        __syncthreads();
        {
            int kbase = ksp * 320 + c * 80;
            #pragma unroll
            for (int j = 0; j < 20; j++) {
                int k = kbase + kk0 + j;
                Bs[kk0 + j][nn] = nok ? Wg[(size_t)k * DIM + n0 + nn] : 0.0f;
            }
        }
        __syncthreads();
        #pragma unroll
        for (int ks = 0; ks < 10; ks++) {
            int kstep = ksp * 40 + c * 10 + ks;
            float4 af[2];
            #pragma unroll
            for (int mt = 0; mt < 2; mt++) {
                int mtile = wm * 2 + mt;
                af[mt] = *(const float4*)(g_FGX + ((size_t)(mtile * KS_GX + kstep) * 32 + lane) * 4);
            }
            #pragma unroll
            for (int nt = 0; nt < 4; nt++) {
                int bn = wn * 32 + nt * 8 + g;
                float b0 = Bs[ks * 8 + t4][bn];
                float b1 = Bs[ks * 8 + t4 + 4][bn];
                #pragma unroll
                for (int mt = 0; mt < 2; mt++) mma8(acc[mt][nt], af[mt], b0, b1);
            }
        }
    }
    #pragma unroll
    for (int mt = 0; mt < 2; mt++) {
        int r0 = wm * 32 + mt * 16 + g, r1 = r0 + 8;
        #pragma unroll
        for (int nt = 0; nt < 4; nt++) {
            int col = n0 + wn * 32 + nt * 8 + t4 * 2;
            if (col < DIM) {
                atomicAdd(&g_A[r0 * DIM + col],     acc[mt][nt][0]);
                atomicAdd(&g_A[r0 * DIM + col + 1], acc[mt][nt][1]);
                atomicAdd(&g_A[r1 * DIM + col],     acc[mt][nt][2]);
                atomicAdd(&g_A[r1 * DIM + col + 1], acc[mt][nt][3]);
            }
        }
    }
}

// ---------------- K5: P0 = sum_r Y_r @ conv_W[r] + GX0 @ W0 (fp32 SIMT, small) ----------------
__global__ void k_gemmP0(const float* __restrict__ convW, const float* __restrict__ W0) {
    const int c0 = blockIdx.x * 64;
    const int kbase = blockIdx.y * 100;
    const int op = blockIdx.z;           // 0..4
    const float* Ab; int lda; const float* Bb;
    if (op < 4) { Ab = g_Y + op * DIM; lda = NREL * DIM; Bb = convW + op * DIM * DIM; }
    else        { Ab = g_GX;           lda = NNODE * DIM; Bb = W0; }
    __shared__ float xs[20][128];
    __shared__ float ws[20][64];
    int tid = threadIdx.x;
    int tx = tid & 15, ty = tid >> 4;
    float acc[8][4];
    #pragma unroll
    for (int i = 0; i < 8; i++)
        #pragma unroll
        for (int j = 0; j < 4; j++) acc[i][j] = 0.0f;
    int lt = tid >> 1, lh = (tid & 1) * 10;
    int wc = tid & 63, wq = (tid >> 6) * 5;
    for (int kb = 0; kb < 100; kb += 20) {
        const float* asrc = Ab + lt * lda + kbase + kb + lh;
        #pragma unroll
        for (int j = 0; j < 10; j++) xs[lh + j][lt] = asrc[j];
        #pragma unroll
        for (int j = 0; j < 5; j++) {
            int kk = wq + j;
            ws[kk][wc] = (c0 + wc < DIM) ? Bb[(kbase + kb + kk) * DIM + c0 + wc] : 0.0f;
        }
        __syncthreads();
        #pragma unroll
        for (int kk = 0; kk < 20; kk++) {
            float4 a0 = *(const float4*)&xs[kk][ty * 8];
            float4 a1 = *(const float4*)&xs[kk][ty * 8 + 4];
            float4 b  = *(const float4*)&ws[kk][tx * 4];
            float av[8] = {a0.x,a0.y,a0.z,a0.w,a1.x,a1.y,a1.z,a1.w};
            float bv[4] = {b.x,b.y,b.z,b.w};
            #pragma unroll
            for (int i = 0; i < 8; i++)
                #pragma unroll
                for (int j = 0; j < 4; j++) acc[i][j] = fmaf(av[i], bv[j], acc[i][j]);
        }
        __syncthreads();
    }
    #pragma unroll
    for (int i = 0; i < 8; i++) {
        int row = ty * 8 + i;
        #pragma unroll
        for (int j = 0; j < 4; j++) {
            int c = c0 + tx * 4 + j;
            if (c < DIM) atomicAdd(&g_P0[row * DIM + c], acc[i][j]);
        }
    }
}

// ---------------- K6: sequential gate recurrence (8-CTA cluster, Ug in registers) ----------------
#define RCH 40   // k-chunk per lane (8 lanes x 40 = 320 >= 300)
__global__ void __cluster_dims__(8, 1, 1) k_recur(const float* __restrict__ Ug) {
    __shared__ __align__(16) float mbuf[2][320];   // double-buffered full m (padded)
    int tid = threadIdx.x;                         // 320 threads
    uint32_t rank;
    asm("mov.u32 %0, %%cluster_ctarank;" : "=r"(rank));
    int g = tid >> 3, s = tid & 7;                 // 40 groups x 8 lanes
    int e = (int)rank * 38 + g;                    // output index (valid when g<38 && e<300)
    bool act = (g < 38) && (e < 300);
    float ug[RCH];
    #pragma unroll
    for (int j = 0; j < RCH; j++) {
        int d = s * RCH + j;
        ug[j] = (act && d < DIM) ? __ldg(&Ug[d * DIM + e]) : 0.0f;
    }
    for (int j = tid; j < 2 * 320; j += blockDim.x) ((float*)mbuf)[j] = 0.0f;
    __syncthreads();
    asm volatile("barrier.cluster.arrive.aligned;" ::: "memory");
    asm volatile("barrier.cluster.wait.aligned;" ::: "memory");

    float a_t = 0.0f, p_t = 0.0f;
    if (act) { a_t = g_A[e]; p_t = g_P0[e]; }

    for (int t = 0; t < S_STEPS; t++) {
        int p = t & 1;
        const float4* mv = reinterpret_cast<const float4*>(&mbuf[p][s * RCH]);
        float ac0 = 0.f, ac1 = 0.f, ac2 = 0.f, ac3 = 0.f;
        #pragma unroll
        for (int q = 0; q < 10; q++) {
            float4 v = mv[q];
            ac0 = fmaf(ug[4 * q + 0], v.x, ac0);
            ac1 = fmaf(ug[4 * q + 1], v.y, ac1);
            ac2 = fmaf(ug[4 * q + 2], v.z, ac2);
            ac3 = fmaf(ug[4 * q + 3], v.w, ac3);
        }
        float acc = (ac0 + ac1) + (ac2 + ac3);
        acc += __shfl_xor_sync(0xFFFFFFFFu, acc, 1);
        acc += __shfl_xor_sync(0xFFFFFFFFu, acc, 2);
        acc += __shfl_xor_sync(0xFFFFFFFFu, acc, 4);
        if (act) {
            float mold = mbuf[p][e];
            float u = 1.0f / (1.0f + __expf(-(acc + a_t)));
            float mn = fmaf(u, p_t - mold, mold);
            st_cluster_f32(smem_u32(&mbuf[1 - p][e]), (uint32_t)s, mn);
            if (s == 0) g_X1[t * DIM + e] = (mn >= 0.0f) ? mn : 0.01f * mn;
        }
        asm volatile("barrier.cluster.arrive.aligned;" ::: "memory");
        if (act && t + 1 < S_STEPS) {
            a_t = g_A [(t + 1) * DIM + e];
            p_t = g_P0[(t + 1) * DIM + e];
        }
        asm volatile("barrier.cluster.wait.aligned;" ::: "memory");
    }
}

// ---------------- K7: logits (tf32 mma) + fused per-block lse partials ----------------
__global__ void k_logits_mma(const float* __restrict__ lin_w, const float* __restrict__ lin_b,
                             float* __restrict__ out) {
    const int v0 = blockIdx.x * 64;
    __shared__ float Bs[80][68];
    __shared__ float2 part[2][128];
    int tid = threadIdx.x;
    int w = tid >> 5, lane = tid & 31;
    int g = lane >> 2, t4 = lane & 3;
    int wm = w & 3, wn = w >> 2;
    float acc[2][4][4];
    #pragma unroll
    for (int a = 0; a < 2; a++)
        #pragma unroll
        for (int b = 0; b < 4; b++)
            #pragma unroll
            for (int c = 0; c < 4; c++) acc[a][b][c] = 0.0f;

    int nn = tid >> 2;                   // 0..63 (row of lin_w tile)
    int kq = (tid & 3) * 20;
    int vrow = v0 + nn;
    bool vok = vrow < VOUT;
    const float* wbase = lin_w + (size_t)vrow * DIM;

    for (int c = 0; c < 4; c++) {
        __syncthreads();
        {
            const float* wr = wbase + c * 80 + kq;
            if (c < 3) {
                #pragma unroll
                for (int j = 0; j < 20; j += 4) {
                    float4 x = vok ? *(const float4*)(wr + j) : make_float4(0.f, 0.f, 0.f, 0.f);
                    Bs[kq + j][nn] = x.x; Bs[kq + j + 1][nn] = x.y;
                    Bs[kq + j + 2][nn] = x.z; Bs[kq + j + 3][nn] = x.w;
                }
            } else {
                #pragma unroll
                for (int j = 0; j < 20; j++) {
                    int k = c * 80 + kq + j;
                    Bs[kq + j][nn] = (vok && k < DIM) ? wr[j] : 0.0f;
                }
            }
        }
        __syncthreads();
        #pragma unroll
        for (int ks = 0; ks < 10; ks++) {
            int kstep = c * 10 + ks;
            float4 af[2];
            #pragma unroll
            for (int mt = 0; mt < 2; mt++) {
                int mtile = wm * 2 + mt;
                af[mt] = *(const float4*)(g_FA1 + ((size_t)(mtile * KS_X1 + kstep) * 32 + lane) * 4);
            }
            #pragma unroll
            for (int nt = 0; nt < 4; nt++) {
                int bn = wn * 32 + nt * 8 + g;
                float b0 = Bs[ks * 8 + t4][bn];
                float b1 = Bs[ks * 8 + t4 + 4][bn];
                #pragma unroll
                for (int mt = 0; mt < 2; mt++) mma8(acc[mt][nt], af[mt], b0, b1);
            }
        }
    }
    // epilogue: + bias, store, accumulate per-row (max,sumexp) over this block's 64 cols
    float mx[4] = {-1e30f, -1e30f, -1e30f, -1e30f};
    float sme[4] = {0.f, 0.f, 0.f, 0.f};
    #pragma unroll
    for (int mt = 0; mt < 2; mt++) {
        int r0 = wm * 32 + mt * 16 + g, r1 = r0 + 8;
        #pragma unroll
        for (int nt = 0; nt < 4; nt++) {
            int vc = v0 + wn * 32 + nt * 8 + t4 * 2;
            if (vc < VOUT) {   // VOUT even, vc even -> vc+1 also valid
                float2 bb = *(const float2*)(lin_b + vc);
                float v00 = acc[mt][nt][0] + bb.x, v01 = acc[mt][nt][1] + bb.y;
                float v10 = acc[mt][nt][2] + bb.x, v11 = acc[mt][nt][3] + bb.y;
                *(float2*)(out + (size_t)r0 * VOUT + vc) = make_float2(v00, v01);
                *(float2*)(out + (size_t)r1 * VOUT + vc) = make_float2(v10, v11);
                lse_upd(mx[2 * mt],     sme[2 * mt],     v00);
                lse_upd(mx[2 * mt],     sme[2 * mt],     v01);
                lse_upd(mx[2 * mt + 1], sme[2 * mt + 1], v10);
                lse_upd(mx[2 * mt + 1], sme[2 * mt + 1], v11);
            }
        }
    }
    // reduce over quad (t4 = 0..3) -> lane t4==0 holds 32-col partial
    #pragma unroll
    for (int i = 0; i < 4; i++) {
        #pragma unroll
        for (int d = 1; d < 4; d <<= 1) {
            float om = __shfl_xor_sync(0xFFFFFFFFu, mx[i], d);
            float os = __shfl_xor_sync(0xFFFFFFFFu, sme[i], d);
            lse_merge(mx[i], sme[i], om, os);
        }
    }
    if (t4 == 0) {
        #pragma unroll
        for (int i = 0; i < 4; i++) {
            int mt = i >> 1, h = i & 1;
            int row = wm * 32 + mt * 16 + g + h * 8;
            part[wn][row] = make_float2(mx[i], sme[i]);
        }
    }
    __syncthreads();
    if (tid < 128) {
        float2 p0 = part[0][tid], p1 = part[1][tid];
        lse_merge(p0.x, p0.y, p1.x, p1.y);
        g_plse[(size_t)blockIdx.x * S_STEPS + tid] = p0;
    }
}

// ---------------- K8: reduce lse partials -> g_sub ----------------
__global__ void k_lse_red() {
    int r = blockIdx.x;
    int tid = threadIdx.x;              // 256
    float M = -1e30f, S = 0.0f;
    for (int b = tid; b < VB; b += 256) {
        float2 p = g_plse[(size_t)b * S_STEPS + r];
        lse_merge(M, S, p.x, p.y);
    }
    __shared__ float sm[256], ss[256];
    sm[tid] = M; ss[tid] = S;
    __syncthreads();
    for (int k = 128; k > 0; k >>= 1) {
        if (tid < k) {
            float m2 = sm[tid + k], s2 = ss[tid + k];
            float Mx = fmaxf(sm[tid], m2);
            ss[tid] = ss[tid] * __expf(sm[tid] - Mx) + s2 * __expf(m2 - Mx);
            sm[tid] = Mx;
        }
        __syncthreads();
    }
    if (tid == 0) g_sub[r] = sm[0] + logf(ss[0]);
}

// ---------------- K9: finalize log_softmax ----------------
__global__ void k_final(float* __restrict__ out) {
    const size_t total4 = (size_t)S_STEPS * VOUT / 4;
    size_t stride = (size_t)gridDim.x * blockDim.x;
    for (size_t i = blockIdx.x * (size_t)blockDim.x + threadIdx.x; i < total4; i += stride) {
        int t = (int)(i / (VOUT / 4));
        float sb = g_sub[t];
        float4 v = ((float4*)out)[i];
        v.x -= sb; v.y -= sb; v.z -= sb; v.w -= sb;
        ((float4*)out)[i] = v;
    }
}

// ---------------- launch ----------------
extern "C" void kernel_launch(void* const* d_in, const int* in_sizes, int n_in,
                              void* d_out, int out_size) {
    (void)in_sizes; (void)n_in; (void)out_size;
    const int*   xind  = (const int*)d_in[0];
    const int*   eidx  = (const int*)d_in[1];
    const int*   etyp  = (const int*)d_in[2];
    const float* X     = (const float*)d_in[3];
    const float* convW = (const float*)d_in[4];
    const float* W0    = (const float*)d_in[5];
    const float* Wg    = (const float*)d_in[6];
    const float* Ug    = (const float*)d_in[7];
    const float* lw    = (const float*)d_in[8];
    const float* lb    = (const float*)d_in[9];
    float* out = (float*)d_out;

    k_gp<<<S_STEPS, 256>>>(xind, eidx, etyp, X, out + (size_t)S_STEPS * VOUT);
    k_fragGX<<<300, 256>>>();
    k_gemmA_mma<<<dim3(5, 30), 256>>>(Wg);
    k_gemmP0<<<dim3(5, 3, 5), 256>>>(convW, W0);
    k_recur<<<8, 320>>>(Ug);
    k_fragX1<<<40, 256>>>();
    k_logits_mma<<<VB, 256>>>(lw, lb, out);
    k_lse_red<<<S_STEPS, 256>>>();
    k_final<<<1600, 256>>>(out);
}

// round 15
// speedup vs baseline: 1.2823x; 1.2823x over previous
#include <cuda_runtime.h>
#include <math.h>
#include <stdint.h>

#define S_STEPS 128
#define NNODE   32
#define DIM     300
#define NREL    4
#define NEDGE   64
#define VOUT    50000
#define VB      ((VOUT + 63) / 64)     // 782 logits col-blocks

#define KS_GX 1200   // ksteps for GX (K=9600)
#define KS_X1 40     // ksteps for X1 (K padded 300->320)

// ---------------- scratch (device globals; no allocs allowed) ----------------
__device__ __align__(16) float g_GX[S_STEPS * NNODE * DIM];   // gathered features [s][n*d]
__device__ __align__(16) float g_Y [S_STEPS * NREL * DIM];    // weighted node sums [s][r][d]
__device__ __align__(16) float g_A [S_STEPS * DIM];           // gxflat @ Wg
__device__ __align__(16) float g_P0[S_STEPS * DIM];           // proposed row 0
__device__ float g_sub[S_STEPS];                              // logsumexp per row
__device__ __align__(16) float g_FGX[8 * KS_GX * 32 * 4];     // frag-order GX (4.7MB)
__device__ __align__(16) float g_FA1[8 * KS_X1 * 32 * 4];     // frag-order X1 (160KB)
__device__ __align__(8)  float2 g_plse[(size_t)VB * S_STEPS]; // per-(vblock,row) partial (max,sumexp)

// ---------------- helpers ----------------
__device__ __forceinline__ uint32_t smem_u32(const void* p) {
    uint32_t a;
    asm("{ .reg .u64 t; cvta.to.shared.u64 t, %1; cvt.u32.u64 %0, t; }" : "=r"(a) : "l"(p));
    return a;
}
__device__ __forceinline__ uint32_t mapa_u32(uint32_t saddr, uint32_t rank) {
    uint32_t remote;
    asm("mapa.shared::cluster.u32 %0, %1, %2;" : "=r"(remote) : "r"(saddr), "r"(rank));
    return remote;
}
// async store to remote CTA smem with tx-count signal on remote mbarrier
__device__ __forceinline__ void st_async_f32(uint32_t raddr, uint32_t rmbar, float v) {
    asm volatile("st.async.shared::cluster.mbarrier::complete_tx::bytes.u32 [%0], %1, [%2];"
                 :: "r"(raddr), "r"(__float_as_uint(v)), "r"(rmbar) : "memory");
}
__device__ __forceinline__ void mbar_init(uint32_t mbar, uint32_t count) {
    asm volatile("mbarrier.init.shared.b64 [%0], %1;" :: "r"(mbar), "r"(count) : "memory");
}
__device__ __forceinline__ void mbar_arrive_expect_tx(uint32_t mbar, uint32_t bytes) {
    asm volatile("mbarrier.arrive.expect_tx.shared.b64 _, [%0], %1;" :: "r"(mbar), "r"(bytes) : "memory");
}
__device__ __forceinline__ void mbar_wait(uint32_t mbar, uint32_t parity) {
    asm volatile(
        "{\n\t"
        ".reg .pred P1;\n\t"
        "WAIT_LOOP_%=:\n\t"
        "mbarrier.try_wait.parity.acquire.cta.shared::cta.b64 P1, [%0], %1, 0x989680;\n\t"
        "@P1 bra.uni WAIT_DONE_%=;\n\t"
        "bra.uni WAIT_LOOP_%=;\n\t"
        "WAIT_DONE_%=:\n\t"
        "}"
        :: "r"(mbar), "r"(parity) : "memory");
}
// D += A(16x8) * B(8x8), tf32 inputs, fp32 accum
__device__ __forceinline__ void mma8(float* c, const float4& a, float b0, float b1) {
    asm volatile(
        "mma.sync.aligned.m16n8k8.row.col.f32.tf32.tf32.f32 "
        "{%0,%1,%2,%3}, {%4,%5,%6,%7}, {%8,%9}, {%0,%1,%2,%3};"
        : "+f"(c[0]), "+f"(c[1]), "+f"(c[2]), "+f"(c[3])
        : "r"(__float_as_uint(a.x)), "r"(__float_as_uint(a.y)),
          "r"(__float_as_uint(a.z)), "r"(__float_as_uint(a.w)),
          "r"(__float_as_uint(b0)), "r"(__float_as_uint(b1)));
}
// online (max, sumexp) update with one value
__device__ __forceinline__ void lse_upd(float& m, float& s, float v) {
    if (v > m) { s = s * __expf(m - v) + 1.0f; m = v; }
    else       { s += __expf(v - m); }
}
__device__ __forceinline__ void lse_merge(float& m, float& s, float om, float os) {
    float M = fmaxf(m, om);
    s = s * __expf(m - M) + os * __expf(om - M);
    m = M;
}

// ---------------- K1: fused gather + graph prep + zero ----------------
__global__ void k_gp(const int* __restrict__ xind, const int* __restrict__ eidx,
                     const int* __restrict__ etyp, const float* __restrict__ X,
                     float* __restrict__ senses) {
    int s = blockIdx.x;
    int tid = threadIdx.x;                              // 256 threads
    __shared__ int idx[NNODE];
    __shared__ __align__(16) float gxs[NNODE * DIM];    // 38.4KB
    __shared__ int ssrc[NEDGE], sdst[NEDGE], styp[NEDGE];
    __shared__ int degc[NREL][NNODE];
    __shared__ float dis[NREL][NNODE];
    __shared__ float w[NREL][NNODE];

    if (tid < NNODE) idx[tid] = xind[s * NNODE + tid];
    if (tid < NEDGE) {
        ssrc[tid] = eidx[s * (2 * NEDGE) + tid];
        sdst[tid] = eidx[s * (2 * NEDGE) + NEDGE + tid];
        styp[tid] = etyp[s * NEDGE + tid];
    }
    if (tid < NREL * NNODE) ((int*)degc)[tid] = 0;
    __syncthreads();

    // gather: X rows -> smem + global
    const float4* Xv = (const float4*)X;
    float4* Gv = (float4*)(g_GX + s * (NNODE * DIM));
    float4* Sv = (float4*)gxs;
    for (int f = tid; f < NNODE * (DIM / 4); f += blockDim.x) {
        int n = f / (DIM / 4), j = f % (DIM / 4);
        float4 v = Xv[(size_t)idx[n] * (DIM / 4) + j];
        Gv[f] = v; Sv[f] = v;
    }
    if (tid < NEDGE) atomicAdd(&degc[styp[tid]][sdst[tid]], 1);
    __syncthreads();
    if (tid < NREL * NNODE) {
        int r = tid >> 5, n = tid & 31;
        dis[r][n] = rsqrtf((float)degc[r][n] + 1.0f);
        ((float*)w)[tid] = 0.0f;
    }
    __syncthreads();
    if (tid < NEDGE && sdst[tid] == 0) {
        int r = styp[tid], sr = ssrc[tid];
        atomicAdd(&w[r][sr], dis[r][sr] * dis[r][0]);
    }
    __syncthreads();
    if (tid < NREL) w[tid][0] += dis[tid][0] * dis[tid][0];
    __syncthreads();
    for (int r = 0; r < NREL; r++) {
        for (int d = tid; d < DIM; d += blockDim.x) {
            float acc = 0.0f;
            #pragma unroll 1
            for (int n = 0; n < NNODE; n++) {
                float ww = w[r][n];
                if (ww != 0.0f) acc = fmaf(ww, gxs[n * DIM + d], acc);
            }
            g_Y[s * (NREL * DIM) + r * DIM + d] = acc;
        }
    }
    // zero accumulators for gemm atomics + senses output
    for (int d = tid; d < DIM; d += blockDim.x) {
        g_A [s * DIM + d] = 0.0f;
        g_P0[s * DIM + d] = 0.0f;
    }
    // zero frag buffer for X1 (recur scatter-writes valid slots; k>=300 stays 0)
    for (int i = blockIdx.x * blockDim.x + tid; i < 8 * KS_X1 * 32 * 4;
         i += gridDim.x * blockDim.x)
        g_FA1[i] = 0.0f;
    if (tid == 0) senses[s] = 0.0f;
}

// ---------------- K2: fragGX (vectorized: 4xLDG.128 -> 4xSTG.128 per thread) ----------------
__global__ void k_fragGX() {
    int t = blockIdx.x * blockDim.x + threadIdx.x;   // 8 * KS_GX * 8 = 76800
    if (t >= 8 * KS_GX * 8) return;
    int g  = t & 7;
    int ks = (t >> 3) % KS_GX;
    int mt = t / (8 * KS_GX);
    int r0 = mt * 16 + g, r1 = r0 + 8;
    const float4* p0 = (const float4*)(g_GX + r0 * (NNODE * DIM) + ks * 8);
    const float4* p1 = (const float4*)(g_GX + r1 * (NNODE * DIM) + ks * 8);
    float4 a0 = p0[0], b0 = p0[1];
    float4 a1 = p1[0], b1 = p1[1];
    float4* o = (float4*)(g_FGX + ((size_t)(mt * KS_GX + ks) * 32 + g * 4) * 4);
    o[0] = make_float4(a0.x, a1.x, b0.x, b1.x);
    o[1] = make_float4(a0.y, a1.y, b0.y, b1.y);
    o[2] = make_float4(a0.z, a1.z, b0.z, b1.z);
    o[3] = make_float4(a0.w, a1.w, b0.w, b1.w);
}

// ---------------- K4: A = GXflat[128,9600] @ Wg[9600,300]  (tf32 mma, k-split atomic) ----------------
__global__ void k_gemmA_mma(const float* __restrict__ Wg) {
    const int n0  = blockIdx.x * 64;     // 5 col tiles
    const int ksp = blockIdx.y;          // 30 k splits, 320 k each
    __shared__ float Bs[80][68];
    int tid = threadIdx.x;
    int w = tid >> 5, lane = tid & 31;
    int g = lane >> 2, t4 = lane & 3;
    int wm = w & 3, wn = w >> 2;
    float acc[2][4][4];
    #pragma unroll
    for (int a = 0; a < 2; a++)
        #pragma unroll
        for (int b = 0; b < 4; b++)
            #pragma unroll
            for (int c = 0; c < 4; c++) acc[a][b][c] = 0.0f;

    int nn  = tid & 63;
    int kk0 = (tid >> 6) * 20;
    bool nok = (n0 + nn) < DIM;
    for (int c = 0; c < 4; c++) {
        __syncthreads();
        {
            int kbase = ksp * 320 + c * 80;
            #pragma unroll
            for (int j = 0; j < 20; j++) {
                int k = kbase + kk0 + j;
                Bs[kk0 + j][nn] = nok ? Wg[(size_t)k * DIM + n0 + nn] : 0.0f;
            }
        }
        __syncthreads();
        #pragma unroll
        for (int ks = 0; ks < 10; ks++) {
            int kstep = ksp * 40 + c * 10 + ks;
            float4 af[2];
            #pragma unroll
            for (int mt = 0; mt < 2; mt++) {
                int mtile = wm * 2 + mt;
                af[mt] = *(const float4*)(g_FGX + ((size_t)(mtile * KS_GX + kstep) * 32 + lane) * 4);
            }
            #pragma unroll
            for (int nt = 0; nt < 4; nt++) {
                int bn = wn * 32 + nt * 8 + g;
                float b0 = Bs[ks * 8 + t4][bn];
                float b1 = Bs[ks * 8 + t4 + 4][bn];
                #pragma unroll
                for (int mt = 0; mt < 2; mt++) mma8(acc[mt][nt], af[mt], b0, b1);
            }
        }
    }
    #pragma unroll
    for (int mt = 0; mt < 2; mt++) {
        int r0 = wm * 32 + mt * 16 + g, r1 = r0 + 8;
        #pragma unroll
        for (int nt = 0; nt < 4; nt++) {
            int col = n0 + wn * 32 + nt * 8 + t4 * 2;
            if (col < DIM) {
                atomicAdd(&g_A[r0 * DIM + col],     acc[mt][nt][0]);
                atomicAdd(&g_A[r0 * DIM + col + 1], acc[mt][nt][1]);
                atomicAdd(&g_A[r1 * DIM + col],     acc[mt][nt][2]);
                atomicAdd(&g_A[r1 * DIM + col + 1], acc[mt][nt][3]);
            }
        }
    }
}

// ---------------- K5: P0 = sum_r Y_r @ conv_W[r] + GX0 @ W0 (fp32 SIMT, 125 CTAs) ----------------
__global__ void k_gemmP0(const float* __restrict__ convW, const float* __restrict__ W0) {
    const int c0 = blockIdx.x * 64;      // 5 col tiles
    const int kbase = blockIdx.y * 60;   // 5 k splits of 60
    const int op = blockIdx.z;           // 0..4
    const float* Ab; int lda; const float* Bb;
    if (op < 4) { Ab = g_Y + op * DIM; lda = NREL * DIM; Bb = convW + op * DIM * DIM; }
    else        { Ab = g_GX;           lda = NNODE * DIM; Bb = W0; }
    __shared__ float xs[20][128];
    __shared__ float ws[20][64];
    int tid = threadIdx.x;
    int tx = tid & 15, ty = tid >> 4;
    float acc[8][4];
    #pragma unroll
    for (int i = 0; i < 8; i++)
        #pragma unroll
        for (int j = 0; j < 4; j++) acc[i][j] = 0.0f;
    int lt = tid >> 1, lh = (tid & 1) * 10;
    int wc = tid & 63, wq = (tid >> 6) * 5;
    for (int kb = 0; kb < 60; kb += 20) {
        const float* asrc = Ab + lt * lda + kbase + kb + lh;
        #pragma unroll
        for (int j = 0; j < 10; j++) xs[lh + j][lt] = asrc[j];
        #pragma unroll
        for (int j = 0; j < 5; j++) {
            int kk = wq + j;
            ws[kk][wc] = (c0 + wc < DIM) ? Bb[(kbase + kb + kk) * DIM + c0 + wc] : 0.0f;
        }
        __syncthreads();
        #pragma unroll
        for (int kk = 0; kk < 20; kk++) {
            float4 a0 = *(const float4*)&xs[kk][ty * 8];
            float4 a1 = *(const float4*)&xs[kk][ty * 8 + 4];
            float4 b  = *(const float4*)&ws[kk][tx * 4];
            float av[8] = {a0.x,a0.y,a0.z,a0.w,a1.x,a1.y,a1.z,a1.w};
            float bv[4] = {b.x,b.y,b.z,b.w};
            #pragma unroll
            for (int i = 0; i < 8; i++)
                #pragma unroll
                for (int j = 0; j < 4; j++) acc[i][j] = fmaf(av[i], bv[j], acc[i][j]);
        }
        __syncthreads();
    }
    #pragma unroll
    for (int i = 0; i < 8; i++) {
        int row = ty * 8 + i;
        #pragma unroll
        for (int j = 0; j < 4; j++) {
            int c = c0 + tx * 4 + j;
            if (c < DIM) atomicAdd(&g_P0[row * DIM + c], acc[i][j]);
        }
    }
}

// ---------------- K6: recurrence (8-CTA cluster, st.async + mbarrier tx, no cluster barrier) ----------------
#define RCH 40   // k-chunk per lane (8 lanes x 40 = 320 >= 300)
__global__ void __cluster_dims__(8, 1, 1) k_recur(const float* __restrict__ Ug) {
    __shared__ __align__(16) float mbuf[2][320];   // double-buffered full m (padded)
    __shared__ __align__(8) unsigned long long mbar[2];
    int tid = threadIdx.x;                         // 320 threads
    uint32_t rank;
    asm("mov.u32 %0, %%cluster_ctarank;" : "=r"(rank));
    int g = tid >> 3, s = tid & 7;                 // 40 groups x 8 lanes
    int e = (int)rank * 38 + g;                    // output index owned by this group
    bool act = (g < 38) && (e < 300);
    float ug[RCH];
    #pragma unroll
    for (int j = 0; j < RCH; j++) {
        int d = s * RCH + j;
        ug[j] = (act && d < DIM) ? __ldg(&Ug[d * DIM + e]) : 0.0f;
    }
    for (int j = tid; j < 2 * 320; j += blockDim.x) ((float*)mbuf)[j] = 0.0f;
    if (tid == 0) {
        mbar_init(smem_u32(&mbar[0]), 1);
        mbar_init(smem_u32(&mbar[1]), 1);
        mbar_arrive_expect_tx(smem_u32(&mbar[0]), 1200);   // arm phase 0 of both
        mbar_arrive_expect_tx(smem_u32(&mbar[1]), 1200);
    }
    __syncthreads();
    asm volatile("barrier.cluster.arrive.aligned;" ::: "memory");
    asm volatile("barrier.cluster.wait.aligned;" ::: "memory");

    // precompute remote addresses: this lane delivers output e to CTA rank s
    uint32_t rbuf[2] = {0, 0}, rbar[2] = {0, 0};
    if (act) {
        rbuf[0] = mapa_u32(smem_u32(&mbuf[0][e]), (uint32_t)s);
        rbuf[1] = mapa_u32(smem_u32(&mbuf[1][e]), (uint32_t)s);
        rbar[0] = mapa_u32(smem_u32(&mbar[0]), (uint32_t)s);
        rbar[1] = mapa_u32(smem_u32(&mbar[1]), (uint32_t)s);
    }
    uint32_t lbar0 = smem_u32(&mbar[0]), lbar1 = smem_u32(&mbar[1]);
    int ph0 = 0, ph1 = 0;

    float a_t = 0.0f, p_t = 0.0f;
    if (act) { a_t = g_A[e]; p_t = g_P0[e]; }      // prefetch t=0

    for (int t = 0; t < S_STEPS; t++) {
        int p = t & 1;
        if (t > 0) {           // buf p written during step t-1; wait its barrier
            if (p) { mbar_wait(lbar1, ph1); ph1 ^= 1; if (tid == 0) mbar_arrive_expect_tx(lbar1, 1200); }
            else   { mbar_wait(lbar0, ph0); ph0 ^= 1; if (tid == 0) mbar_arrive_expect_tx(lbar0, 1200); }
        }
        const float4* mv = reinterpret_cast<const float4*>(&mbuf[p][s * RCH]);
        float ac0 = 0.f, ac1 = 0.f, ac2 = 0.f, ac3 = 0.f;
        #pragma unroll
        for (int q = 0; q < 10; q++) {
            float4 v = mv[q];
            ac0 = fmaf(ug[4 * q + 0], v.x, ac0);
            ac1 = fmaf(ug[4 * q + 1], v.y, ac1);
            ac2 = fmaf(ug[4 * q + 2], v.z, ac2);
            ac3 = fmaf(ug[4 * q + 3], v.w, ac3);
        }
        float acc = (ac0 + ac1) + (ac2 + ac3);
        acc += __shfl_xor_sync(0xFFFFFFFFu, acc, 1);
        acc += __shfl_xor_sync(0xFFFFFFFFu, acc, 2);
        acc += __shfl_xor_sync(0xFFFFFFFFu, acc, 4);
        if (act) {
            float mold = mbuf[p][e];
            float u = 1.0f / (1.0f + __expf(-(acc + a_t)));
            float mn = fmaf(u, p_t - mold, mold);
            if (t + 1 < S_STEPS) st_async_f32(rbuf[1 - p], rbar[1 - p], mn);
            if (s == 0) {       // scatter leaky(mn) directly into mma fragment order
                float lv = (mn >= 0.0f) ? mn : 0.01f * mn;
                int mt = t >> 4, rpos = t & 15;
                int half = rpos >> 3, gg = rpos & 7;
                int ks = e >> 3, kmod = e & 7;
                int t4 = kmod & 3, hi = kmod >> 2;
                int comp = half + (hi << 1);
                int lane = gg * 4 + t4;
                g_FA1[((size_t)(mt * KS_X1 + ks) * 32 + lane) * 4 + comp] = lv;
            }
            if (t + 1 < S_STEPS) {
                a_t = g_A [(t + 1) * DIM + e];
                p_t = g_P0[(t + 1) * DIM + e];
            }
        }
    }
    asm volatile("barrier.cluster.arrive.aligned;" ::: "memory");
    asm volatile("barrier.cluster.wait.aligned;" ::: "memory");
}

// ---------------- K7: logits (tf32 mma) + fused per-block lse partials ----------------
__global__ void k_logits_mma(const float* __restrict__ lin_w, const float* __restrict__ lin_b,
                             float* __restrict__ out) {
    const int v0 = blockIdx.x * 64;
    __shared__ float Bs[80][68];
    __shared__ float2 part[2][128];
    int tid = threadIdx.x;
    int w = tid >> 5, lane = tid & 31;
    int g = lane >> 2, t4 = lane & 3;
    int wm = w & 3, wn = w >> 2;
    float acc[2][4][4];
    #pragma unroll
    for (int a = 0; a < 2; a++)
        #pragma unroll
        for (int b = 0; b < 4; b++)
            #pragma unroll
            for (int c = 0; c < 4; c++) acc[a][b][c] = 0.0f;

    int nn = tid >> 2;                   // 0..63 (row of lin_w tile)
    int kq = (tid & 3) * 20;
    int vrow = v0 + nn;
    bool vok = vrow < VOUT;
    const float* wbase = lin_w + (size_t)vrow * DIM;

    for (int c = 0; c < 4; c++) {
        __syncthreads();
        {
            const float* wr = wbase + c * 80 + kq;
            if (c < 3) {
                #pragma unroll
                for (int j = 0; j < 20; j += 4) {
                    float4 x = vok ? *(const float4*)(wr + j) : make_float4(0.f, 0.f, 0.f, 0.f);
                    Bs[kq + j][nn] = x.x; Bs[kq + j + 1][nn] = x.y;
                    Bs[kq + j + 2][nn] = x.z; Bs[kq + j + 3][nn] = x.w;
                }
            } else {
                #pragma unroll
                for (int j = 0; j < 20; j++) {
                    int k = c * 80 + kq + j;
                    Bs[kq + j][nn] = (vok && k < DIM) ? wr[j] : 0.0f;
                }
            }
        }
        __syncthreads();
        #pragma unroll
        for (int ks = 0; ks < 10; ks++) {
            int kstep = c * 10 + ks;
            float4 af[2];
            #pragma unroll
            for (int mt = 0; mt < 2; mt++) {
                int mtile = wm * 2 + mt;
                af[mt] = *(const float4*)(g_FA1 + ((size_t)(mtile * KS_X1 + kstep) * 32 + lane) * 4);
            }
            #pragma unroll
            for (int nt = 0; nt < 4; nt++) {
                int bn = wn * 32 + nt * 8 + g;
                float b0 = Bs[ks * 8 + t4][bn];
                float b1 = Bs[ks * 8 + t4 + 4][bn];
                #pragma unroll
                for (int mt = 0; mt < 2; mt++) mma8(acc[mt][nt], af[mt], b0, b1);
            }
        }
    }
    // epilogue: + bias, store, accumulate per-row (max,sumexp) over this block's 64 cols
    float mx[4] = {-1e30f, -1e30f, -1e30f, -1e30f};
    float sme[4] = {0.f, 0.f, 0.f, 0.f};
    #pragma unroll
    for (int mt = 0; mt < 2; mt++) {
        int r0 = wm * 32 + mt * 16 + g, r1 = r0 + 8;
        #pragma unroll
        for (int nt = 0; nt < 4; nt++) {
            int vc = v0 + wn * 32 + nt * 8 + t4 * 2;
            if (vc < VOUT) {   // VOUT even, vc even -> vc+1 also valid
                float2 bb = *(const float2*)(lin_b + vc);
                float v00 = acc[mt][nt][0] + bb.x, v01 = acc[mt][nt][1] + bb.y;
                float v10 = acc[mt][nt][2] + bb.x, v11 = acc[mt][nt][3] + bb.y;
                *(float2*)(out + (size_t)r0 * VOUT + vc) = make_float2(v00, v01);
                *(float2*)(out + (size_t)r1 * VOUT + vc) = make_float2(v10, v11);
                lse_upd(mx[2 * mt],     sme[2 * mt],     v00);
                lse_upd(mx[2 * mt],     sme[2 * mt],     v01);
                lse_upd(mx[2 * mt + 1], sme[2 * mt + 1], v10);
                lse_upd(mx[2 * mt + 1], sme[2 * mt + 1], v11);
            }
        }
    }
    // reduce over quad (t4 = 0..3)
    #pragma unroll
    for (int i = 0; i < 4; i++) {
        #pragma unroll
        for (int d = 1; d < 4; d <<= 1) {
            float om = __shfl_xor_sync(0xFFFFFFFFu, mx[i], d);
            float os = __shfl_xor_sync(0xFFFFFFFFu, sme[i], d);
            lse_merge(mx[i], sme[i], om, os);
        }
    }
    if (t4 == 0) {
        #pragma unroll
        for (int i = 0; i < 4; i++) {
            int mt = i >> 1, h = i & 1;
            int row = wm * 32 + mt * 16 + g + h * 8;
            part[wn][row] = make_float2(mx[i], sme[i]);
        }
    }
    __syncthreads();
    if (tid < 128) {
        float2 p0 = part[0][tid], p1 = part[1][tid];
        lse_merge(p0.x, p0.y, p1.x, p1.y);
        g_plse[(size_t)blockIdx.x * S_STEPS + tid] = p0;
    }
}

// ---------------- K8: reduce lse partials -> g_sub ----------------
__global__ void k_lse_red() {
    int r = blockIdx.x;
    int tid = threadIdx.x;              // 256
    float M = -1e30f, S = 0.0f;
    for (int b = tid; b < VB; b += 256) {
        float2 p = g_plse[(size_t)b * S_STEPS + r];
        lse_merge(M, S, p.x, p.y);
    }
    __shared__ float sm[256], ss[256];
    sm[tid] = M; ss[tid] = S;
    __syncthreads();
    for (int k = 128; k > 0; k >>= 1) {
        if (tid < k) {
            float m2 = sm[tid + k], s2 = ss[tid + k];
            float Mx = fmaxf(sm[tid], m2);
            ss[tid] = ss[tid] * __expf(sm[tid] - Mx) + s2 * __expf(m2 - Mx);
            sm[tid] = Mx;
        }
        __syncthreads();
    }
    if (tid == 0) g_sub[r] = sm[0] + logf(ss[0]);
}

// ---------------- K9: finalize log_softmax ----------------
__global__ void k_final(float* __restrict__ out) {
    const size_t total4 = (size_t)S_STEPS * VOUT / 4;
    size_t stride = (size_t)gridDim.x * blockDim.x;
    for (size_t i = blockIdx.x * (size_t)blockDim.x + threadIdx.x; i < total4; i += stride) {
        int t = (int)(i / (VOUT / 4));
        float sb = g_sub[t];
        float4 v = ((float4*)out)[i];
        v.x -= sb; v.y -= sb; v.z -= sb; v.w -= sb;
        ((float4*)out)[i] = v;
    }
}

// ---------------- launch ----------------
extern "C" void kernel_launch(void* const* d_in, const int* in_sizes, int n_in,
                              void* d_out, int out_size) {
    (void)in_sizes; (void)n_in; (void)out_size;
    const int*   xind  = (const int*)d_in[0];
    const int*   eidx  = (const int*)d_in[1];
    const int*   etyp  = (const int*)d_in[2];
    const float* X     = (const float*)d_in[3];
    const float* convW = (const float*)d_in[4];
    const float* W0    = (const float*)d_in[5];
    const float* Wg    = (const float*)d_in[6];
    const float* Ug    = (const float*)d_in[7];
    const float* lw    = (const float*)d_in[8];
    const float* lb    = (const float*)d_in[9];
    float* out = (float*)d_out;

    k_gp<<<S_STEPS, 256>>>(xind, eidx, etyp, X, out + (size_t)S_STEPS * VOUT);
    k_fragGX<<<300, 256>>>();
    k_gemmA_mma<<<dim3(5, 30), 256>>>(Wg);
    k_gemmP0<<<dim3(5, 5, 5), 256>>>(convW, W0);
    k_recur<<<8, 320>>>(Ug);
    k_logits_mma<<<VB, 256>>>(lw, lb, out);
    k_lse_red<<<S_STEPS, 256>>>();
    k_final<<<1600, 256>>>(out);
}